// round 6
// baseline (speedup 1.0000x reference)
#include <cuda_runtime.h>

// ThreeBodyAggregation — moment-factorized implementation.
//
// agg_l(b,i) = sum_{j,k} w_j w_k P_l(u_j . u_k) is computed exactly via
// weighted direction moments (Legendre monomial expansion):
//   agg0 = S^2
//   agg1 = |V|^2
//   agg2 = 1.5*||M||_F^2 - 0.5*S^2
//   agg3 = 2.5*||T||^2   - 1.5*|V|^2
// with S = sum w, V_x = sum w x, M_xy = sum w x y, T_xyz = sum w x y z.
// This turns the O(N^3) triple sum into an O(N) reduction per (b,i).

#define B_   4
#define N_   160
#define R_   64
#define EMB_ 128
#define HID_ 128
#define RPB  2          // rows (b,i) per block
#define NTHREADS 256
#define EPS_LN 1e-5f

__global__ __launch_bounds__(NTHREADS)
void tba_kernel(const float* __restrict__ rbf,     // (B,N,N,R)
                const float* __restrict__ r_hat,   // (B,N,N,3)
                const float* __restrict__ mask,    // (B,N,N)
                const float* __restrict__ w_rad,   // (1,R)
                const float* __restrict__ b_rad,   // (1,)
                const float* __restrict__ w1,      // (HID,4)
                const float* __restrict__ b1,      // (HID,)
                const float* __restrict__ w2,      // (EMB,HID)
                const float* __restrict__ b2,      // (EMB,)
                const float* __restrict__ gamma,   // (EMB,)
                const float* __restrict__ beta,    // (EMB,)
                float* __restrict__ out)           // (B,N,EMB)
{
    __shared__ float s_wrad[R_];
    __shared__ float s_w[N_];
    __shared__ float s_red[8][20];
    __shared__ float s_agg[RPB][4];
    __shared__ float s_h[RPB][HID_];

    const int tid  = threadIdx.x;
    const int lane = tid & 31;
    const int warp = tid >> 5;

    if (tid < R_) s_wrad[tid] = w_rad[tid];
    const float brad = b_rad[0];
    const int row0 = blockIdx.x * RPB;
    __syncthreads();

    const float wr0 = s_wrad[2 * lane];
    const float wr1 = s_wrad[2 * lane + 1];

    for (int t = 0; t < RPB; ++t) {
        const int row = row0 + t;
        const float2* rbf_row =
            reinterpret_cast<const float2*>(rbf + (size_t)row * (N_ * R_));

        // ---- Phase A: w_j = sigmoid(rbf[j,:] . w_rad + b_rad) * mask[j]
        // warp w handles j = w*20 .. w*20+19; per-lane float2 load is a
        // fully coalesced 256B line pair per j.
        #pragma unroll 4
        for (int jj = 0; jj < 20; ++jj) {
            const int j = warp * 20 + jj;
            float2 v2 = rbf_row[j * (R_ / 2) + lane];
            float v = fmaf(v2.x, wr0, v2.y * wr1);
            #pragma unroll
            for (int off = 16; off; off >>= 1)
                v += __shfl_xor_sync(0xffffffffu, v, off);
            if (lane == 0) {
                float m = mask[row * N_ + j];
                s_w[j] = m * __frcp_rn(1.f + __expf(-(v + brad)));
            }
        }
        __syncthreads();

        // ---- Phase B: weighted direction moments (20 accumulators)
        float acc[20];
        #pragma unroll
        for (int q = 0; q < 20; ++q) acc[q] = 0.f;
        if (tid < N_) {
            const float w = s_w[tid];
            const float* rh = r_hat + ((size_t)row * N_ + tid) * 3;
            const float x = rh[0], y = rh[1], z = rh[2];
            const float wx = w * x, wy = w * y, wz = w * z;
            const float wxx = wx * x, wyy = wy * y, wzz = wz * z;
            const float wxy = wx * y, wxz = wx * z, wyz = wy * z;
            acc[0]  = w;
            acc[1]  = wx;  acc[2]  = wy;  acc[3]  = wz;
            acc[4]  = wxx; acc[5]  = wyy; acc[6]  = wzz;
            acc[7]  = wxy; acc[8]  = wxz; acc[9]  = wyz;
            acc[10] = wxx * x; acc[11] = wyy * y; acc[12] = wzz * z;
            acc[13] = wxx * y; acc[14] = wxx * z;
            acc[15] = wyy * x; acc[16] = wyy * z;
            acc[17] = wzz * x; acc[18] = wzz * y;
            acc[19] = wxy * z;
        }
        #pragma unroll
        for (int q = 0; q < 20; ++q) {
            float v = acc[q];
            #pragma unroll
            for (int off = 16; off; off >>= 1)
                v += __shfl_xor_sync(0xffffffffu, v, off);
            if (lane == 0) s_red[warp][q] = v;
        }
        __syncthreads();

        if (tid == 0) {
            float m[20];
            #pragma unroll
            for (int q = 0; q < 20; ++q) {
                float v = 0.f;
                #pragma unroll
                for (int u = 0; u < 8; ++u) v += s_red[u][q];
                m[q] = v;
            }
            const float S  = m[0];
            const float V2 = m[1]*m[1] + m[2]*m[2] + m[3]*m[3];
            const float Q2 = m[4]*m[4] + m[5]*m[5] + m[6]*m[6]
                           + 2.f * (m[7]*m[7] + m[8]*m[8] + m[9]*m[9]);
            const float Q3 = m[10]*m[10] + m[11]*m[11] + m[12]*m[12]
                           + 3.f * (m[13]*m[13] + m[14]*m[14] + m[15]*m[15]
                                  + m[16]*m[16] + m[17]*m[17] + m[18]*m[18])
                           + 6.f * m[19]*m[19];
            s_agg[t][0] = S * S;
            s_agg[t][1] = V2;
            s_agg[t][2] = 1.5f * Q2 - 0.5f * S * S;
            s_agg[t][3] = 2.5f * Q3 - 1.5f * V2;
        }
        __syncthreads();
    }

    // ---- Phase C: h = silu(agg @ w1^T + b1)
    if (tid < HID_) {
        const float4 wv1 = reinterpret_cast<const float4*>(w1)[tid];
        const float bb = b1[tid];
        #pragma unroll
        for (int t = 0; t < RPB; ++t) {
            float hv = fmaf(s_agg[t][0], wv1.x,
                       fmaf(s_agg[t][1], wv1.y,
                       fmaf(s_agg[t][2], wv1.z,
                       fmaf(s_agg[t][3], wv1.w, bb))));
            hv = hv * __frcp_rn(1.f + __expf(-hv));
            s_h[t][tid] = hv;
        }
    }
    __syncthreads();

    // ---- out = h @ w2^T + b2, then LayerNorm
    float ov[RPB];
    #pragma unroll
    for (int t = 0; t < RPB; ++t) ov[t] = 0.f;

    if (tid < EMB_) {
        const float4* w2r = reinterpret_cast<const float4*>(w2) + tid * (HID_ / 4);
        #pragma unroll 8
        for (int h4 = 0; h4 < HID_ / 4; ++h4) {
            const float4 wv = w2r[h4];
            #pragma unroll
            for (int t = 0; t < RPB; ++t) {
                const float4 hv = reinterpret_cast<const float4*>(s_h[t])[h4];
                ov[t] = fmaf(wv.x, hv.x,
                        fmaf(wv.y, hv.y,
                        fmaf(wv.z, hv.z,
                        fmaf(wv.w, hv.w, ov[t]))));
            }
        }
        const float bb = b2[tid];
        #pragma unroll
        for (int t = 0; t < RPB; ++t) ov[t] += bb;
    }

    // LN mean: reduce over 128 outputs held by warps 0..3
    if (warp < 4) {
        #pragma unroll
        for (int t = 0; t < RPB; ++t) {
            float v = ov[t];
            #pragma unroll
            for (int off = 16; off; off >>= 1)
                v += __shfl_xor_sync(0xffffffffu, v, off);
            if (lane == 0) s_red[warp][t] = v;
        }
    }
    __syncthreads();
    float mu[RPB];
    #pragma unroll
    for (int t = 0; t < RPB; ++t)
        mu[t] = (s_red[0][t] + s_red[1][t] + s_red[2][t] + s_red[3][t])
                * (1.f / EMB_);

    // LN variance (two-pass; writes to disjoint slots so no extra sync needed
    // before the writes, one sync before the reads)
    if (warp < 4) {
        #pragma unroll
        for (int t = 0; t < RPB; ++t) {
            const float d = ov[t] - mu[t];
            float v = d * d;
            #pragma unroll
            for (int off = 16; off; off >>= 1)
                v += __shfl_xor_sync(0xffffffffu, v, off);
            if (lane == 0) s_red[warp][RPB + t] = v;
        }
    }
    __syncthreads();

    if (tid < EMB_) {
        const float g = gamma[tid];
        const float be = beta[tid];
        #pragma unroll
        for (int t = 0; t < RPB; ++t) {
            const float var = (s_red[0][RPB + t] + s_red[1][RPB + t]
                             + s_red[2][RPB + t] + s_red[3][RPB + t])
                             * (1.f / EMB_);
            const float y = (ov[t] - mu[t]) * rsqrtf(var + EPS_LN);
            out[(size_t)(row0 + t) * EMB_ + tid] = fmaf(y, g, be);
        }
    }
}

extern "C" void kernel_launch(void* const* d_in, const int* in_sizes, int n_in,
                              void* d_out, int out_size)
{
    const float* rbf    = (const float*)d_in[0];
    const float* r_hat  = (const float*)d_in[1];
    const float* mask   = (const float*)d_in[2];
    const float* w_rad  = (const float*)d_in[3];
    const float* b_rad  = (const float*)d_in[4];
    const float* w1     = (const float*)d_in[5];
    const float* b1     = (const float*)d_in[6];
    const float* w2     = (const float*)d_in[7];
    const float* b2     = (const float*)d_in[8];
    const float* gamma  = (const float*)d_in[9];
    const float* beta   = (const float*)d_in[10];
    float* out = (float*)d_out;

    const int n_rows = B_ * N_;                 // 640
    dim3 grid(n_rows / RPB);                    // 320 blocks
    tba_kernel<<<grid, NTHREADS>>>(rbf, r_hat, mask, w_rad, b_rad,
                                   w1, b1, w2, b2, gamma, beta, out);
}

// round 7
// speedup vs baseline: 1.4721x; 1.4721x over previous
#include <cuda_runtime.h>

// ThreeBodyAggregation — moment-factorized, two-kernel split.
//
// K1 (DRAM-bound stream): per row (b,i), compute w_j = sigmoid(rbf.w_rad+b)*mask,
// then the weighted direction moments -> agg[row][0..3] (Legendre identity):
//   agg0 = S^2
//   agg1 = |V|^2
//   agg2 = 1.5*||M||_F^2 - 0.5*S^2
//   agg3 = 2.5*||T||^2   - 1.5*|V|^2
// K2 (L2/compute): silu MLP, w2 GEMV (8 rows/block to amortize w2), LayerNorm.

#define B_   4
#define N_   160
#define R_   64
#define EMB_ 128
#define HID_ 128
#define EPS_LN 1e-5f
#define RPB2 8

__device__ float g_agg[B_ * N_ * 4];

// ---------------------------------------------------------------- K1
__global__ __launch_bounds__(256)
void tba_k1(const float* __restrict__ rbf,     // (B,N,N,R)
            const float* __restrict__ r_hat,   // (B,N,N,3)
            const float* __restrict__ mask,    // (B,N,N)
            const float* __restrict__ w_rad,   // (1,R)
            const float* __restrict__ b_rad)   // (1,)
{
    __shared__ float s_w[N_];
    __shared__ float s_red[8][20];

    const int tid   = threadIdx.x;
    const int lane  = tid & 31;
    const int warp  = tid >> 5;
    const int lane4 = tid & 3;
    const int row   = blockIdx.x;
    const float brad = b_rad[0];

    // Per-thread w_rad chunk: 16 consecutive floats (4 float4s) in registers.
    const float4* wr4 = reinterpret_cast<const float4*>(w_rad);
    float4 wr[4];
    #pragma unroll
    for (int k = 0; k < 4; ++k) wr[k] = wr4[lane4 * 4 + k];

    const float4* rbf4 =
        reinterpret_cast<const float4*>(rbf + (size_t)row * (N_ * R_));

    // ---- Phase A: 4 lanes per j, 4 independent float4 loads per lane (MLP=4).
    // 256 threads cover 64 j's per pass; 3 passes cover N=160.
    #pragma unroll
    for (int pass = 0; pass < 3; ++pass) {
        const int j = pass * 64 + (tid >> 2);
        if (j < N_) {
            const float4* p = rbf4 + j * (R_ / 4) + lane4 * 4;
            const float4 a0 = p[0], a1 = p[1], a2 = p[2], a3 = p[3];
            float v;
            v = a0.x * wr[0].x;
            v = fmaf(a0.y, wr[0].y, v);
            v = fmaf(a0.z, wr[0].z, v);
            v = fmaf(a0.w, wr[0].w, v);
            v = fmaf(a1.x, wr[1].x, v);
            v = fmaf(a1.y, wr[1].y, v);
            v = fmaf(a1.z, wr[1].z, v);
            v = fmaf(a1.w, wr[1].w, v);
            v = fmaf(a2.x, wr[2].x, v);
            v = fmaf(a2.y, wr[2].y, v);
            v = fmaf(a2.z, wr[2].z, v);
            v = fmaf(a2.w, wr[2].w, v);
            v = fmaf(a3.x, wr[3].x, v);
            v = fmaf(a3.y, wr[3].y, v);
            v = fmaf(a3.z, wr[3].z, v);
            v = fmaf(a3.w, wr[3].w, v);
            v += __shfl_xor_sync(0xffffffffu, v, 1);
            v += __shfl_xor_sync(0xffffffffu, v, 2);
            if (lane4 == 0) {
                const float m = mask[row * N_ + j];
                s_w[j] = m * __frcp_rn(1.f + __expf(-(v + brad)));
            }
        }
    }
    __syncthreads();

    // ---- Phase B: weighted direction moments (20 accumulators).
    float acc[20];
    #pragma unroll
    for (int q = 0; q < 20; ++q) acc[q] = 0.f;
    if (tid < N_) {
        const float w = s_w[tid];
        const float* rh = r_hat + ((size_t)row * N_ + tid) * 3;
        const float x = rh[0], y = rh[1], z = rh[2];
        const float wx = w * x, wy = w * y, wz = w * z;
        const float wxx = wx * x, wyy = wy * y, wzz = wz * z;
        const float wxy = wx * y, wxz = wx * z, wyz = wy * z;
        acc[0]  = w;
        acc[1]  = wx;  acc[2]  = wy;  acc[3]  = wz;
        acc[4]  = wxx; acc[5]  = wyy; acc[6]  = wzz;
        acc[7]  = wxy; acc[8]  = wxz; acc[9]  = wyz;
        acc[10] = wxx * x; acc[11] = wyy * y; acc[12] = wzz * z;
        acc[13] = wxx * y; acc[14] = wxx * z;
        acc[15] = wyy * x; acc[16] = wyy * z;
        acc[17] = wzz * x; acc[18] = wzz * y;
        acc[19] = wxy * z;
    }
    #pragma unroll
    for (int q = 0; q < 20; ++q) {
        float v = acc[q];
        #pragma unroll
        for (int off = 16; off; off >>= 1)
            v += __shfl_xor_sync(0xffffffffu, v, off);
        if (lane == 0) s_red[warp][q] = v;
    }
    __syncthreads();

    if (tid == 0) {
        float m[20];
        #pragma unroll
        for (int q = 0; q < 20; ++q) {
            float v = 0.f;
            #pragma unroll
            for (int u = 0; u < 8; ++u) v += s_red[u][q];
            m[q] = v;
        }
        const float S  = m[0];
        const float V2 = m[1]*m[1] + m[2]*m[2] + m[3]*m[3];
        const float Q2 = m[4]*m[4] + m[5]*m[5] + m[6]*m[6]
                       + 2.f * (m[7]*m[7] + m[8]*m[8] + m[9]*m[9]);
        const float Q3 = m[10]*m[10] + m[11]*m[11] + m[12]*m[12]
                       + 3.f * (m[13]*m[13] + m[14]*m[14] + m[15]*m[15]
                              + m[16]*m[16] + m[17]*m[17] + m[18]*m[18])
                       + 6.f * m[19]*m[19];
        float4 agg;
        agg.x = S * S;
        agg.y = V2;
        agg.z = 1.5f * Q2 - 0.5f * S * S;
        agg.w = 2.5f * Q3 - 1.5f * V2;
        reinterpret_cast<float4*>(g_agg)[row] = agg;
    }
}

// ---------------------------------------------------------------- K2
__global__ __launch_bounds__(256)
void tba_k2(const float* __restrict__ w1,     // (HID,4)
            const float* __restrict__ b1,     // (HID,)
            const float* __restrict__ w2,     // (EMB,HID)
            const float* __restrict__ b2,     // (EMB,)
            const float* __restrict__ gamma,  // (EMB,)
            const float* __restrict__ beta,   // (EMB,)
            float* __restrict__ out)          // (B,N,EMB)
{
    __shared__ float s_h[RPB2][HID_];
    __shared__ float s_red[4][2 * RPB2];

    const int tid  = threadIdx.x;
    const int lane = tid & 31;
    const int warp = tid >> 5;
    const int row0 = blockIdx.x * RPB2;

    // ---- h = silu(agg @ w1^T + b1), 256 threads over RPB2 x HID grid.
    {
        const int hcol  = tid & 127;
        const int rbase = tid >> 7;  // 0 or 1
        const float4 wv1 = reinterpret_cast<const float4*>(w1)[hcol];
        const float bb = b1[hcol];
        #pragma unroll
        for (int it = 0; it < RPB2 / 2; ++it) {
            const int r = rbase + 2 * it;
            const float4 a = reinterpret_cast<const float4*>(g_agg)[row0 + r];
            float hv = fmaf(a.x, wv1.x,
                       fmaf(a.y, wv1.y,
                       fmaf(a.z, wv1.z,
                       fmaf(a.w, wv1.w, bb))));
            hv = hv * __frcp_rn(1.f + __expf(-hv));
            s_h[r][hcol] = hv;
        }
    }
    __syncthreads();

    // ---- out = h @ w2^T + b2 (register-blocked over RPB2 rows), then LN.
    float ov[RPB2];
    #pragma unroll
    for (int t = 0; t < RPB2; ++t) ov[t] = 0.f;

    if (tid < EMB_) {
        const float4* w2r = reinterpret_cast<const float4*>(w2) + tid * (HID_ / 4);
        #pragma unroll 4
        for (int h4 = 0; h4 < HID_ / 4; ++h4) {
            const float4 wv = w2r[h4];
            #pragma unroll
            for (int t = 0; t < RPB2; ++t) {
                const float4 hv = reinterpret_cast<const float4*>(s_h[t])[h4];
                ov[t] = fmaf(wv.x, hv.x,
                        fmaf(wv.y, hv.y,
                        fmaf(wv.z, hv.z,
                        fmaf(wv.w, hv.w, ov[t]))));
            }
        }
        const float bb = b2[tid];
        #pragma unroll
        for (int t = 0; t < RPB2; ++t) ov[t] += bb;
    }

    // LN mean over EMB (held by warps 0..3).
    if (warp < 4) {
        #pragma unroll
        for (int t = 0; t < RPB2; ++t) {
            float v = ov[t];
            #pragma unroll
            for (int off = 16; off; off >>= 1)
                v += __shfl_xor_sync(0xffffffffu, v, off);
            if (lane == 0) s_red[warp][t] = v;
        }
    }
    __syncthreads();
    float mu[RPB2];
    #pragma unroll
    for (int t = 0; t < RPB2; ++t)
        mu[t] = (s_red[0][t] + s_red[1][t] + s_red[2][t] + s_red[3][t])
                * (1.f / EMB_);

    // LN variance (disjoint slots).
    if (warp < 4) {
        #pragma unroll
        for (int t = 0; t < RPB2; ++t) {
            const float d = ov[t] - mu[t];
            float v = d * d;
            #pragma unroll
            for (int off = 16; off; off >>= 1)
                v += __shfl_xor_sync(0xffffffffu, v, off);
            if (lane == 0) s_red[warp][RPB2 + t] = v;
        }
    }
    __syncthreads();

    if (tid < EMB_) {
        const float g  = gamma[tid];
        const float be = beta[tid];
        #pragma unroll
        for (int t = 0; t < RPB2; ++t) {
            const float var = (s_red[0][RPB2 + t] + s_red[1][RPB2 + t]
                             + s_red[2][RPB2 + t] + s_red[3][RPB2 + t])
                             * (1.f / EMB_);
            const float y = (ov[t] - mu[t]) * rsqrtf(var + EPS_LN);
            out[(size_t)(row0 + t) * EMB_ + tid] = fmaf(y, g, be);
        }
    }
}

extern "C" void kernel_launch(void* const* d_in, const int* in_sizes, int n_in,
                              void* d_out, int out_size)
{
    const float* rbf    = (const float*)d_in[0];
    const float* r_hat  = (const float*)d_in[1];
    const float* mask   = (const float*)d_in[2];
    const float* w_rad  = (const float*)d_in[3];
    const float* b_rad  = (const float*)d_in[4];
    const float* w1     = (const float*)d_in[5];
    const float* b1     = (const float*)d_in[6];
    const float* w2     = (const float*)d_in[7];
    const float* b2     = (const float*)d_in[8];
    const float* gamma  = (const float*)d_in[9];
    const float* beta   = (const float*)d_in[10];
    float* out = (float*)d_out;

    tba_k1<<<B_ * N_, 256>>>(rbf, r_hat, mask, w_rad, b_rad);
    tba_k2<<<(B_ * N_) / RPB2, 256>>>(w1, b1, w2, b2, gamma, beta, out);
}

// round 8
// speedup vs baseline: 1.6294x; 1.1068x over previous
#include <cuda_runtime.h>

// ThreeBodyAggregation — moment-factorized, two-kernel split.
//
// K1 (DRAM stream, 640 blocks): per row (b,i), w_j = sigmoid(rbf.w_rad+b)*mask,
// then weighted direction moments -> agg[row][0..3] via the Legendre identity:
//   agg0 = S^2
//   agg1 = |V|^2
//   agg2 = 1.5*||M||_F^2 - 0.5*S^2
//   agg3 = 2.5*||T||^2   - 1.5*|V|^2
// K2 (160 blocks): silu MLP + coalesced warp-per-output w2 GEMV + LayerNorm.

#define B_   4
#define N_   160
#define R_   64
#define EMB_ 128
#define HID_ 128
#define EPS_LN 1e-5f
#define RPB2 4

__device__ float4 g_agg[B_ * N_];

// ---------------------------------------------------------------- K1
__global__ __launch_bounds__(256)
void tba_k1(const float* __restrict__ rbf,     // (B,N,N,R)
            const float* __restrict__ r_hat,   // (B,N,N,3)
            const float* __restrict__ mask,    // (B,N,N)
            const float* __restrict__ w_rad,   // (1,R)
            const float* __restrict__ b_rad)   // (1,)
{
    __shared__ float s_w[N_];
    __shared__ float s_red[8][20];

    const int tid   = threadIdx.x;
    const int lane  = tid & 31;
    const int warp  = tid >> 5;
    const int lane4 = tid & 3;
    const int row   = blockIdx.x;
    const float brad = b_rad[0];

    // Per-thread w_rad chunk: 16 consecutive floats (4 float4s) in registers.
    const float4* wr4 = reinterpret_cast<const float4*>(w_rad);
    float4 wr[4];
    #pragma unroll
    for (int k = 0; k < 4; ++k) wr[k] = wr4[lane4 * 4 + k];

    const float4* rbf4 =
        reinterpret_cast<const float4*>(rbf + (size_t)row * (N_ * R_));

    // ---- Phase A: 4 lanes per j. Front-batch ALL loads (3 passes x 4 float4
    // per thread = MLP 12) with clamped indices, then reduce.
    float4 a[3][4];
    #pragma unroll
    for (int p = 0; p < 3; ++p) {
        int j  = p * 64 + (tid >> 2);
        int jc = (j < N_) ? j : (N_ - 1);
        const float4* ptr = rbf4 + jc * (R_ / 4) + lane4 * 4;
        a[p][0] = ptr[0];
        a[p][1] = ptr[1];
        a[p][2] = ptr[2];
        a[p][3] = ptr[3];
    }

    #pragma unroll
    for (int p = 0; p < 3; ++p) {
        const int j = p * 64 + (tid >> 2);
        float v;
        v = a[p][0].x * wr[0].x;
        v = fmaf(a[p][0].y, wr[0].y, v);
        v = fmaf(a[p][0].z, wr[0].z, v);
        v = fmaf(a[p][0].w, wr[0].w, v);
        v = fmaf(a[p][1].x, wr[1].x, v);
        v = fmaf(a[p][1].y, wr[1].y, v);
        v = fmaf(a[p][1].z, wr[1].z, v);
        v = fmaf(a[p][1].w, wr[1].w, v);
        v = fmaf(a[p][2].x, wr[2].x, v);
        v = fmaf(a[p][2].y, wr[2].y, v);
        v = fmaf(a[p][2].z, wr[2].z, v);
        v = fmaf(a[p][2].w, wr[2].w, v);
        v = fmaf(a[p][3].x, wr[3].x, v);
        v = fmaf(a[p][3].y, wr[3].y, v);
        v = fmaf(a[p][3].z, wr[3].z, v);
        v = fmaf(a[p][3].w, wr[3].w, v);
        v += __shfl_xor_sync(0xffffffffu, v, 1);
        v += __shfl_xor_sync(0xffffffffu, v, 2);
        if (lane4 == 0 && j < N_) {
            const float m = mask[row * N_ + j];
            s_w[j] = m * __frcp_rn(1.f + __expf(-(v + brad)));
        }
    }
    __syncthreads();

    // ---- Phase B: weighted direction moments (20 accumulators).
    float acc[20];
    #pragma unroll
    for (int q = 0; q < 20; ++q) acc[q] = 0.f;
    if (tid < N_) {
        const float w = s_w[tid];
        const float* rh = r_hat + ((size_t)row * N_ + tid) * 3;
        const float x = rh[0], y = rh[1], z = rh[2];
        const float wx = w * x, wy = w * y, wz = w * z;
        const float wxx = wx * x, wyy = wy * y, wzz = wz * z;
        const float wxy = wx * y, wxz = wx * z, wyz = wy * z;
        acc[0]  = w;
        acc[1]  = wx;  acc[2]  = wy;  acc[3]  = wz;
        acc[4]  = wxx; acc[5]  = wyy; acc[6]  = wzz;
        acc[7]  = wxy; acc[8]  = wxz; acc[9]  = wyz;
        acc[10] = wxx * x; acc[11] = wyy * y; acc[12] = wzz * z;
        acc[13] = wxx * y; acc[14] = wxx * z;
        acc[15] = wyy * x; acc[16] = wyy * z;
        acc[17] = wzz * x; acc[18] = wzz * y;
        acc[19] = wxy * z;
    }
    #pragma unroll
    for (int q = 0; q < 20; ++q) {
        float v = acc[q];
        #pragma unroll
        for (int off = 16; off; off >>= 1)
            v += __shfl_xor_sync(0xffffffffu, v, off);
        if (lane == 0) s_red[warp][q] = v;
    }
    __syncthreads();

    if (tid == 0) {
        float m[20];
        #pragma unroll
        for (int q = 0; q < 20; ++q) {
            float v = 0.f;
            #pragma unroll
            for (int u = 0; u < 8; ++u) v += s_red[u][q];
            m[q] = v;
        }
        const float S  = m[0];
        const float V2 = m[1]*m[1] + m[2]*m[2] + m[3]*m[3];
        const float Q2 = m[4]*m[4] + m[5]*m[5] + m[6]*m[6]
                       + 2.f * (m[7]*m[7] + m[8]*m[8] + m[9]*m[9]);
        const float Q3 = m[10]*m[10] + m[11]*m[11] + m[12]*m[12]
                       + 3.f * (m[13]*m[13] + m[14]*m[14] + m[15]*m[15]
                              + m[16]*m[16] + m[17]*m[17] + m[18]*m[18])
                       + 6.f * m[19]*m[19];
        float4 agg;
        agg.x = S * S;
        agg.y = V2;
        agg.z = 1.5f * Q2 - 0.5f * S * S;
        agg.w = 2.5f * Q3 - 1.5f * V2;
        g_agg[row] = agg;
    }
}

// ---------------------------------------------------------------- K2
__global__ __launch_bounds__(256)
void tba_k2(const float* __restrict__ w1,     // (HID,4)
            const float* __restrict__ b1,     // (HID,)
            const float* __restrict__ w2,     // (EMB,HID)
            const float* __restrict__ b2,     // (EMB,)
            const float* __restrict__ gamma,  // (EMB,)
            const float* __restrict__ beta,   // (EMB,)
            float* __restrict__ out)          // (B,N,EMB)
{
    __shared__ float s_h[RPB2][HID_];
    __shared__ float s_o[RPB2][EMB_];
    __shared__ float s_red[4][2 * RPB2];

    const int tid  = threadIdx.x;
    const int lane = tid & 31;
    const int warp = tid >> 5;
    const int row0 = blockIdx.x * RPB2;

    // ---- Phase C: h = silu(agg @ w1^T + b1)
    {
        const int hcol  = tid & 127;
        const int rbase = tid >> 7;  // 0 or 1
        const float4 wv1 = reinterpret_cast<const float4*>(w1)[hcol];
        const float bb = b1[hcol];
        #pragma unroll
        for (int it = 0; it < RPB2 / 2; ++it) {
            const int r = rbase + 2 * it;
            const float4 ag = g_agg[row0 + r];
            float hv = fmaf(ag.x, wv1.x,
                       fmaf(ag.y, wv1.y,
                       fmaf(ag.z, wv1.z,
                       fmaf(ag.w, wv1.w, bb))));
            hv = hv * __frcp_rn(1.f + __expf(-hv));
            s_h[r][hcol] = hv;
        }
    }
    __syncthreads();

    // Per-lane h slice of every row stays in registers.
    float4 hv[RPB2];
    #pragma unroll
    for (int t = 0; t < RPB2; ++t)
        hv[t] = reinterpret_cast<const float4*>(s_h[t])[lane];

    // ---- GEMV: warp w handles outputs e = 16w..16w+15; lanes span HID.
    // Coalesced w2 loads (consecutive lanes -> consecutive float4s), 16
    // independent loads per warp unrolled => MLP 16.
    const float4* w2v = reinterpret_cast<const float4*>(w2);
    #pragma unroll
    for (int ee = 0; ee < 16; ++ee) {
        const int e = warp * 16 + ee;
        const float4 wv = w2v[e * 32 + lane];
        float acc[RPB2];
        #pragma unroll
        for (int t = 0; t < RPB2; ++t)
            acc[t] = fmaf(wv.x, hv[t].x,
                     fmaf(wv.y, hv[t].y,
                     fmaf(wv.z, hv[t].z,
                          wv.w * hv[t].w)));
        // 6-shuffle packed reduce: ends with lane k (k<4) holding row-k dot.
        // Stage 1 (bit 0): merge (acc0,acc1) and (acc2,acc3).
        float keepA = (lane & 1) ? acc[1] : acc[0];
        float sendA = (lane & 1) ? acc[0] : acc[1];
        keepA += __shfl_xor_sync(0xffffffffu, sendA, 1);
        float keepB = (lane & 1) ? acc[3] : acc[2];
        float sendB = (lane & 1) ? acc[2] : acc[3];
        keepB += __shfl_xor_sync(0xffffffffu, sendB, 1);
        // Stage 2 (bit 1): merge A/B types.
        float keep = (lane & 2) ? keepB : keepA;
        float send = (lane & 2) ? keepA : keepB;
        keep += __shfl_xor_sync(0xffffffffu, send, 2);
        // Butterfly over bits 2..4.
        keep += __shfl_xor_sync(0xffffffffu, keep, 4);
        keep += __shfl_xor_sync(0xffffffffu, keep, 8);
        keep += __shfl_xor_sync(0xffffffffu, keep, 16);
        if (lane < RPB2) s_o[lane][e] = keep;
    }
    __syncthreads();

    // ---- LayerNorm. Threads 0..127 own output column e=tid across rows.
    float ov[RPB2];
    #pragma unroll
    for (int t = 0; t < RPB2; ++t) ov[t] = 0.f;
    if (tid < EMB_) {
        const float bb = b2[tid];
        #pragma unroll
        for (int t = 0; t < RPB2; ++t) ov[t] = s_o[t][tid] + bb;
    }

    if (warp < 4) {
        #pragma unroll
        for (int t = 0; t < RPB2; ++t) {
            float v = ov[t];
            #pragma unroll
            for (int off = 16; off; off >>= 1)
                v += __shfl_xor_sync(0xffffffffu, v, off);
            if (lane == 0) s_red[warp][t] = v;
        }
    }
    __syncthreads();
    float mu[RPB2];
    #pragma unroll
    for (int t = 0; t < RPB2; ++t)
        mu[t] = (s_red[0][t] + s_red[1][t] + s_red[2][t] + s_red[3][t])
                * (1.f / EMB_);

    if (warp < 4) {
        #pragma unroll
        for (int t = 0; t < RPB2; ++t) {
            const float d = ov[t] - mu[t];
            float v = d * d;
            #pragma unroll
            for (int off = 16; off; off >>= 1)
                v += __shfl_xor_sync(0xffffffffu, v, off);
            if (lane == 0) s_red[warp][RPB2 + t] = v;
        }
    }
    __syncthreads();

    if (tid < EMB_) {
        const float g  = gamma[tid];
        const float be = beta[tid];
        #pragma unroll
        for (int t = 0; t < RPB2; ++t) {
            const float var = (s_red[0][RPB2 + t] + s_red[1][RPB2 + t]
                             + s_red[2][RPB2 + t] + s_red[3][RPB2 + t])
                             * (1.f / EMB_);
            const float y = (ov[t] - mu[t]) * rsqrtf(var + EPS_LN);
            out[(size_t)(row0 + t) * EMB_ + tid] = fmaf(y, g, be);
        }
    }
}

extern "C" void kernel_launch(void* const* d_in, const int* in_sizes, int n_in,
                              void* d_out, int out_size)
{
    const float* rbf    = (const float*)d_in[0];
    const float* r_hat  = (const float*)d_in[1];
    const float* mask   = (const float*)d_in[2];
    const float* w_rad  = (const float*)d_in[3];
    const float* b_rad  = (const float*)d_in[4];
    const float* w1     = (const float*)d_in[5];
    const float* b1     = (const float*)d_in[6];
    const float* w2     = (const float*)d_in[7];
    const float* b2     = (const float*)d_in[8];
    const float* gamma  = (const float*)d_in[9];
    const float* beta   = (const float*)d_in[10];
    float* out = (float*)d_out;

    tba_k1<<<B_ * N_, 256>>>(rbf, r_hat, mask, w_rad, b_rad);
    tba_k2<<<(B_ * N_) / RPB2, 256>>>(w1, b1, w2, b2, gamma, beta, out);
}

// round 9
// speedup vs baseline: 1.8520x; 1.1366x over previous
#include <cuda_runtime.h>

// ThreeBodyAggregation — moment-factorized, fully fused single kernel.
//
// agg_l(b,i) = sum_{j,k} w_j w_k P_l(u_j.u_k), computed exactly via weighted
// direction moments (Legendre monomial expansion):
//   agg0 = S^2
//   agg1 = |V|^2
//   agg2 = 1.5*||M||_F^2 - 0.5*S^2
//   agg3 = 2.5*||T||^2   - 1.5*|V|^2
// Then h = silu(agg @ w1^T + b1), o = h @ w2^T + b2, LayerNorm(o).
//
// Phase A is arranged so each LDG.128 covers 512B contiguous per warp
// (2 rbf j-rows), i.e. 4 cache lines per instruction (L1tex-minimal).

#define B_   4
#define N_   160
#define R_   64
#define EMB_ 128
#define HID_ 128
#define EPS_LN 1e-5f
#define RPB  2

__global__ __launch_bounds__(256)
void tba_fused(const float* __restrict__ rbf,     // (B,N,N,R)
               const float* __restrict__ r_hat,   // (B,N,N,3)
               const float* __restrict__ mask,    // (B,N,N)
               const float* __restrict__ w_rad,   // (1,R)
               const float* __restrict__ b_rad,   // (1,)
               const float* __restrict__ w1,      // (HID,4)
               const float* __restrict__ b1,      // (HID,)
               const float* __restrict__ w2,      // (EMB,HID)
               const float* __restrict__ b2,      // (EMB,)
               const float* __restrict__ gamma,   // (EMB,)
               const float* __restrict__ beta,    // (EMB,)
               float* __restrict__ out)           // (B,N,EMB)
{
    __shared__ float s_w[N_];
    __shared__ float s_red[8][20];
    __shared__ float s_m[20];
    __shared__ float s_agg[RPB][4];
    __shared__ float s_h[RPB][HID_];
    __shared__ float s_o[RPB][EMB_];
    __shared__ float s_ln[4][2 * RPB];

    const int tid  = threadIdx.x;
    const int lane = tid & 31;
    const int warp = tid >> 5;
    const int row0 = blockIdx.x * RPB;
    const float brad = b_rad[0];

    // Each lane owns one float4 chunk of w_rad (row = 16 float4s; lane&15).
    const float4 wr = reinterpret_cast<const float4*>(w_rad)[lane & 15];

    for (int t = 0; t < RPB; ++t) {
        const int row = row0 + t;
        const float4* rbf4 =
            reinterpret_cast<const float4*>(rbf + (size_t)row * (N_ * R_));

        // ---- Phase A: warp w handles j = 20w .. 20w+19, two j-rows per pass
        // (lane>>4 selects the row within the pair). One LDG.128 per lane per
        // pass; the warp's 32 float4s are 512B contiguous. All 10 passes'
        // loads front-batched (MLP = 10).
        const int jb = warp * 20 + (lane >> 4);
        float4 a[10];
        #pragma unroll
        for (int p = 0; p < 10; ++p)
            a[p] = rbf4[(size_t)(jb + 2 * p) * (R_ / 4) + (lane & 15)];

        #pragma unroll
        for (int p = 0; p < 10; ++p) {
            float v = a[p].x * wr.x;
            v = fmaf(a[p].y, wr.y, v);
            v = fmaf(a[p].z, wr.z, v);
            v = fmaf(a[p].w, wr.w, v);
            v += __shfl_xor_sync(0xffffffffu, v, 1);
            v += __shfl_xor_sync(0xffffffffu, v, 2);
            v += __shfl_xor_sync(0xffffffffu, v, 4);
            v += __shfl_xor_sync(0xffffffffu, v, 8);
            if ((lane & 15) == 0) {
                const int j = jb + 2 * p;
                s_w[j] = mask[row * N_ + j]
                       * __frcp_rn(1.f + __expf(-(v + brad)));
            }
        }
        __syncthreads();

        // ---- Phase B: weighted direction moments (20 accumulators).
        float acc[20];
        #pragma unroll
        for (int q = 0; q < 20; ++q) acc[q] = 0.f;
        if (tid < N_) {
            const float w = s_w[tid];
            const float* rh = r_hat + ((size_t)row * N_ + tid) * 3;
            const float x = rh[0], y = rh[1], z = rh[2];
            const float wx = w * x, wy = w * y, wz = w * z;
            const float wxx = wx * x, wyy = wy * y, wzz = wz * z;
            const float wxy = wx * y, wxz = wx * z, wyz = wy * z;
            acc[0]  = w;
            acc[1]  = wx;  acc[2]  = wy;  acc[3]  = wz;
            acc[4]  = wxx; acc[5]  = wyy; acc[6]  = wzz;
            acc[7]  = wxy; acc[8]  = wxz; acc[9]  = wyz;
            acc[10] = wxx * x; acc[11] = wyy * y; acc[12] = wzz * z;
            acc[13] = wxx * y; acc[14] = wxx * z;
            acc[15] = wyy * x; acc[16] = wyy * z;
            acc[17] = wzz * x; acc[18] = wzz * y;
            acc[19] = wxy * z;
        }
        #pragma unroll
        for (int q = 0; q < 20; ++q) {
            float v = acc[q];
            #pragma unroll
            for (int off = 16; off; off >>= 1)
                v += __shfl_xor_sync(0xffffffffu, v, off);
            if (lane == 0) s_red[warp][q] = v;
        }
        __syncthreads();

        if (tid < 20) {
            float v = 0.f;
            #pragma unroll
            for (int u = 0; u < 8; ++u) v += s_red[u][tid];
            s_m[tid] = v;
        }
        __syncthreads();

        if (tid == 0) {
            float m[20];
            #pragma unroll
            for (int q = 0; q < 20; ++q) m[q] = s_m[q];
            const float S  = m[0];
            const float V2 = m[1]*m[1] + m[2]*m[2] + m[3]*m[3];
            const float Q2 = m[4]*m[4] + m[5]*m[5] + m[6]*m[6]
                           + 2.f * (m[7]*m[7] + m[8]*m[8] + m[9]*m[9]);
            const float Q3 = m[10]*m[10] + m[11]*m[11] + m[12]*m[12]
                           + 3.f * (m[13]*m[13] + m[14]*m[14] + m[15]*m[15]
                                  + m[16]*m[16] + m[17]*m[17] + m[18]*m[18])
                           + 6.f * m[19]*m[19];
            s_agg[t][0] = S * S;
            s_agg[t][1] = V2;
            s_agg[t][2] = 1.5f * Q2 - 0.5f * S * S;
            s_agg[t][3] = 2.5f * Q3 - 1.5f * V2;
        }
        __syncthreads();
    }

    // ---- Phase C: h = silu(agg @ w1^T + b1). 256 threads = 2 rows x 128 cols.
    {
        const int hcol = tid & 127;
        const int r    = tid >> 7;
        const float4 wv1 = reinterpret_cast<const float4*>(w1)[hcol];
        const float bb = b1[hcol];
        float hv = fmaf(s_agg[r][0], wv1.x,
                   fmaf(s_agg[r][1], wv1.y,
                   fmaf(s_agg[r][2], wv1.z,
                   fmaf(s_agg[r][3], wv1.w, bb))));
        hv = hv * __frcp_rn(1.f + __expf(-hv));
        s_h[r][hcol] = hv;
    }
    __syncthreads();

    // Per-lane h slice of both rows in registers.
    float4 hv[RPB];
    #pragma unroll
    for (int t = 0; t < RPB; ++t)
        hv[t] = reinterpret_cast<const float4*>(s_h[t])[lane];

    // ---- GEMV: warp w handles outputs e = 16w..16w+15; lanes span HID.
    // Coalesced w2 loads, 16 independent loads per warp (MLP 16).
    const float4* w2v = reinterpret_cast<const float4*>(w2);
    #pragma unroll
    for (int ee = 0; ee < 16; ++ee) {
        const int e = warp * 16 + ee;
        const float4 wv = w2v[e * 32 + lane];
        float acc0 = fmaf(wv.x, hv[0].x, fmaf(wv.y, hv[0].y,
                     fmaf(wv.z, hv[0].z, wv.w * hv[0].w)));
        float acc1 = fmaf(wv.x, hv[1].x, fmaf(wv.y, hv[1].y,
                     fmaf(wv.z, hv[1].z, wv.w * hv[1].w)));
        // Packed 5-shuffle reduce: even lanes carry row0, odd lanes row1.
        float keep = (lane & 1) ? acc1 : acc0;
        float send = (lane & 1) ? acc0 : acc1;
        keep += __shfl_xor_sync(0xffffffffu, send, 1);
        keep += __shfl_xor_sync(0xffffffffu, keep, 2);
        keep += __shfl_xor_sync(0xffffffffu, keep, 4);
        keep += __shfl_xor_sync(0xffffffffu, keep, 8);
        keep += __shfl_xor_sync(0xffffffffu, keep, 16);
        if (lane < RPB) s_o[lane][e] = keep;
    }
    __syncthreads();

    // ---- LayerNorm. Threads 0..127 own output column e = tid across rows.
    float ov[RPB];
    #pragma unroll
    for (int t = 0; t < RPB; ++t) ov[t] = 0.f;
    if (tid < EMB_) {
        const float bb = b2[tid];
        #pragma unroll
        for (int t = 0; t < RPB; ++t) ov[t] = s_o[t][tid] + bb;
    }

    if (warp < 4) {
        #pragma unroll
        for (int t = 0; t < RPB; ++t) {
            float v = ov[t];
            #pragma unroll
            for (int off = 16; off; off >>= 1)
                v += __shfl_xor_sync(0xffffffffu, v, off);
            if (lane == 0) s_ln[warp][t] = v;
        }
    }
    __syncthreads();
    float mu[RPB];
    #pragma unroll
    for (int t = 0; t < RPB; ++t)
        mu[t] = (s_ln[0][t] + s_ln[1][t] + s_ln[2][t] + s_ln[3][t])
                * (1.f / EMB_);

    if (warp < 4) {
        #pragma unroll
        for (int t = 0; t < RPB; ++t) {
            const float d = ov[t] - mu[t];
            float v = d * d;
            #pragma unroll
            for (int off = 16; off; off >>= 1)
                v += __shfl_xor_sync(0xffffffffu, v, off);
            if (lane == 0) s_ln[warp][RPB + t] = v;
        }
    }
    __syncthreads();

    if (tid < EMB_) {
        const float g  = gamma[tid];
        const float be = beta[tid];
        #pragma unroll
        for (int t = 0; t < RPB; ++t) {
            const float var = (s_ln[0][RPB + t] + s_ln[1][RPB + t]
                             + s_ln[2][RPB + t] + s_ln[3][RPB + t])
                             * (1.f / EMB_);
            const float y = (ov[t] - mu[t]) * rsqrtf(var + EPS_LN);
            out[(size_t)(row0 + t) * EMB_ + tid] = fmaf(y, g, be);
        }
    }
}

extern "C" void kernel_launch(void* const* d_in, const int* in_sizes, int n_in,
                              void* d_out, int out_size)
{
    const float* rbf    = (const float*)d_in[0];
    const float* r_hat  = (const float*)d_in[1];
    const float* mask   = (const float*)d_in[2];
    const float* w_rad  = (const float*)d_in[3];
    const float* b_rad  = (const float*)d_in[4];
    const float* w1     = (const float*)d_in[5];
    const float* b1     = (const float*)d_in[6];
    const float* w2     = (const float*)d_in[7];
    const float* b2     = (const float*)d_in[8];
    const float* gamma  = (const float*)d_in[9];
    const float* beta   = (const float*)d_in[10];
    float* out = (float*)d_out;

    tba_fused<<<(B_ * N_) / RPB, 256>>>(rbf, r_hat, mask, w_rad, b_rad,
                                        w1, b1, w2, b2, gamma, beta, out);
}

// round 10
// speedup vs baseline: 2.0634x; 1.1142x over previous
#include <cuda_runtime.h>

// ThreeBodyAggregation — moment-factorized, fully fused, 1 row per block.
//
// agg_l(b,i) = sum_{j,k} w_j w_k P_l(u_j.u_k) computed exactly via weighted
// direction moments (Legendre monomial expansion):
//   agg0 = S^2
//   agg1 = |V|^2
//   agg2 = 1.5*||M||_F^2 - 0.5*S^2
//   agg3 = 2.5*||T||^2   - 1.5*|V|^2
// Then h = silu(agg @ w1^T + b1), o = h @ w2^T + b2, LayerNorm(o).

#define B_   4
#define N_   160
#define R_   64
#define EMB_ 128
#define HID_ 128
#define EPS_LN 1e-5f

__global__ __launch_bounds__(256)
void tba_fused(const float* __restrict__ rbf,     // (B,N,N,R)
               const float* __restrict__ r_hat,   // (B,N,N,3)
               const float* __restrict__ mask,    // (B,N,N)
               const float* __restrict__ w_rad,   // (1,R)
               const float* __restrict__ b_rad,   // (1,)
               const float* __restrict__ w1,      // (HID,4)
               const float* __restrict__ b1,      // (HID,)
               const float* __restrict__ w2,      // (EMB,HID)
               const float* __restrict__ b2,      // (EMB,)
               const float* __restrict__ gamma,   // (EMB,)
               const float* __restrict__ beta,    // (EMB,)
               float* __restrict__ out)           // (B,N,EMB)
{
    __shared__ float s_w[N_];
    __shared__ float s_red[8][20];
    __shared__ float s_agg[4];
    __shared__ float s_h[HID_];
    __shared__ float s_o[EMB_];
    __shared__ float s_ln[4][2];

    const int tid  = threadIdx.x;
    const int lane = tid & 31;
    const int warp = tid >> 5;
    const int row  = blockIdx.x;
    const float brad = b_rad[0];

    // 8 lanes per j-row. Lane c = lane&7 owns w_rad float4s c and c+8.
    const int c = lane & 7;
    const float4* wr4 = reinterpret_cast<const float4*>(w_rad);
    const float4 wr0 = wr4[c];
    const float4 wr1 = wr4[c + 8];

    const float4* rbf4 =
        reinterpret_cast<const float4*>(rbf + (size_t)row * (N_ * R_));

    // ---- Phase A: warp w covers j = 20w..20w+19; 4 j-rows per pass
    // (lane>>3 selects the row), 5 passes, 2 LDG.128 per lane per pass.
    // Each LDG's 32 lane-addresses split into 4 rows x 128B contiguous
    // (4 cache lines per instruction). All 10 loads front-batched (MLP=10).
    const int jb = warp * 20 + (lane >> 3);
    float4 a0[5], a1[5];
    #pragma unroll
    for (int p = 0; p < 5; ++p) {
        const size_t base = (size_t)(jb + 4 * p) * (R_ / 4);
        a0[p] = rbf4[base + c];
        a1[p] = rbf4[base + c + 8];
    }

    #pragma unroll
    for (int p = 0; p < 5; ++p) {
        float v = a0[p].x * wr0.x;
        v = fmaf(a0[p].y, wr0.y, v);
        v = fmaf(a0[p].z, wr0.z, v);
        v = fmaf(a0[p].w, wr0.w, v);
        v = fmaf(a1[p].x, wr1.x, v);
        v = fmaf(a1[p].y, wr1.y, v);
        v = fmaf(a1[p].z, wr1.z, v);
        v = fmaf(a1[p].w, wr1.w, v);
        v += __shfl_xor_sync(0xffffffffu, v, 1);
        v += __shfl_xor_sync(0xffffffffu, v, 2);
        v += __shfl_xor_sync(0xffffffffu, v, 4);
        if (c == 0) {
            const int j = jb + 4 * p;
            s_w[j] = mask[row * N_ + j]
                   * __frcp_rn(1.f + __expf(-(v + brad)));
        }
    }
    __syncthreads();

    // ---- Phase B: weighted direction moments (20 accumulators).
    float acc[20];
    #pragma unroll
    for (int q = 0; q < 20; ++q) acc[q] = 0.f;
    if (tid < N_) {
        const float w = s_w[tid];
        const float* rh = r_hat + ((size_t)row * N_ + tid) * 3;
        const float x = rh[0], y = rh[1], z = rh[2];
        const float wx = w * x, wy = w * y, wz = w * z;
        const float wxx = wx * x, wyy = wy * y, wzz = wz * z;
        const float wxy = wx * y, wxz = wx * z, wyz = wy * z;
        acc[0]  = w;
        acc[1]  = wx;  acc[2]  = wy;  acc[3]  = wz;
        acc[4]  = wxx; acc[5]  = wyy; acc[6]  = wzz;
        acc[7]  = wxy; acc[8]  = wxz; acc[9]  = wyz;
        acc[10] = wxx * x; acc[11] = wyy * y; acc[12] = wzz * z;
        acc[13] = wxx * y; acc[14] = wxx * z;
        acc[15] = wyy * x; acc[16] = wyy * z;
        acc[17] = wzz * x; acc[18] = wzz * y;
        acc[19] = wxy * z;
    }
    #pragma unroll
    for (int q = 0; q < 20; ++q) {
        float v = acc[q];
        #pragma unroll
        for (int off = 16; off; off >>= 1)
            v += __shfl_xor_sync(0xffffffffu, v, off);
        if (lane == 0) s_red[warp][q] = v;
    }
    __syncthreads();

    if (tid == 0) {
        float m[20];
        #pragma unroll
        for (int q = 0; q < 20; ++q) {
            float v = 0.f;
            #pragma unroll
            for (int u = 0; u < 8; ++u) v += s_red[u][q];
            m[q] = v;
        }
        const float S  = m[0];
        const float V2 = m[1]*m[1] + m[2]*m[2] + m[3]*m[3];
        const float Q2 = m[4]*m[4] + m[5]*m[5] + m[6]*m[6]
                       + 2.f * (m[7]*m[7] + m[8]*m[8] + m[9]*m[9]);
        const float Q3 = m[10]*m[10] + m[11]*m[11] + m[12]*m[12]
                       + 3.f * (m[13]*m[13] + m[14]*m[14] + m[15]*m[15]
                              + m[16]*m[16] + m[17]*m[17] + m[18]*m[18])
                       + 6.f * m[19]*m[19];
        s_agg[0] = S * S;
        s_agg[1] = V2;
        s_agg[2] = 1.5f * Q2 - 0.5f * S * S;
        s_agg[3] = 2.5f * Q3 - 1.5f * V2;
    }
    __syncthreads();

    // ---- Phase C: h = silu(agg @ w1^T + b1). First 128 threads.
    if (tid < HID_) {
        const float4 wv1 = reinterpret_cast<const float4*>(w1)[tid];
        float hv = fmaf(s_agg[0], wv1.x,
                   fmaf(s_agg[1], wv1.y,
                   fmaf(s_agg[2], wv1.z,
                   fmaf(s_agg[3], wv1.w, b1[tid]))));
        hv = hv * __frcp_rn(1.f + __expf(-hv));
        s_h[tid] = hv;
    }
    __syncthreads();

    // Per-lane h slice in registers.
    const float4 hv = reinterpret_cast<const float4*>(s_h)[lane];

    // ---- GEMV: warp w handles outputs e = 16w..16w+15, paired (even lanes
    // carry e0 partials, odd lanes e1) so 2 outputs cost 5 shuffles.
    const float4* w2v = reinterpret_cast<const float4*>(w2);
    #pragma unroll
    for (int ee = 0; ee < 8; ++ee) {
        const int e0 = warp * 16 + 2 * ee;
        const float4 wv0 = w2v[e0 * 32 + lane];
        const float4 wv1 = w2v[(e0 + 1) * 32 + lane];
        float acc0 = fmaf(wv0.x, hv.x, fmaf(wv0.y, hv.y,
                     fmaf(wv0.z, hv.z, wv0.w * hv.w)));
        float acc1 = fmaf(wv1.x, hv.x, fmaf(wv1.y, hv.y,
                     fmaf(wv1.z, hv.z, wv1.w * hv.w)));
        float keep = (lane & 1) ? acc1 : acc0;
        float send = (lane & 1) ? acc0 : acc1;
        keep += __shfl_xor_sync(0xffffffffu, send, 1);
        keep += __shfl_xor_sync(0xffffffffu, keep, 2);
        keep += __shfl_xor_sync(0xffffffffu, keep, 4);
        keep += __shfl_xor_sync(0xffffffffu, keep, 8);
        keep += __shfl_xor_sync(0xffffffffu, keep, 16);
        if (lane < 2) s_o[e0 + lane] = keep;
    }
    __syncthreads();

    // ---- LayerNorm over EMB=128 (warps 0..3 hold one value each thread).
    float ov = 0.f;
    if (tid < EMB_) ov = s_o[tid] + b2[tid];

    if (warp < 4) {
        float v = ov;
        #pragma unroll
        for (int off = 16; off; off >>= 1)
            v += __shfl_xor_sync(0xffffffffu, v, off);
        if (lane == 0) s_ln[warp][0] = v;
    }
    __syncthreads();
    const float mu = (s_ln[0][0] + s_ln[1][0] + s_ln[2][0] + s_ln[3][0])
                     * (1.f / EMB_);

    if (warp < 4) {
        const float d = ov - mu;
        float v = d * d;
        #pragma unroll
        for (int off = 16; off; off >>= 1)
            v += __shfl_xor_sync(0xffffffffu, v, off);
        if (lane == 0) s_ln[warp][1] = v;
    }
    __syncthreads();

    if (tid < EMB_) {
        const float var = (s_ln[0][1] + s_ln[1][1] + s_ln[2][1] + s_ln[3][1])
                          * (1.f / EMB_);
        const float y = (ov - mu) * rsqrtf(var + EPS_LN);
        out[(size_t)row * EMB_ + tid] = fmaf(y, gamma[tid], beta[tid]);
    }
}

extern "C" void kernel_launch(void* const* d_in, const int* in_sizes, int n_in,
                              void* d_out, int out_size)
{
    const float* rbf    = (const float*)d_in[0];
    const float* r_hat  = (const float*)d_in[1];
    const float* mask   = (const float*)d_in[2];
    const float* w_rad  = (const float*)d_in[3];
    const float* b_rad  = (const float*)d_in[4];
    const float* w1     = (const float*)d_in[5];
    const float* b1     = (const float*)d_in[6];
    const float* w2     = (const float*)d_in[7];
    const float* b2     = (const float*)d_in[8];
    const float* gamma  = (const float*)d_in[9];
    const float* beta   = (const float*)d_in[10];
    float* out = (float*)d_out;

    tba_fused<<<B_ * N_, 256>>>(rbf, r_hat, mask, w_rad, b_rad,
                                w1, b1, w2, b2, gamma, beta, out);
}

// round 11
// speedup vs baseline: 2.0678x; 1.0021x over previous
#include <cuda_runtime.h>

// ThreeBodyAggregation — moment-factorized, fully fused, 1 row per block.
//
// agg_l(b,i) = sum_{j,k} w_j w_k P_l(u_j.u_k) computed exactly via weighted
// direction moments (Legendre monomial expansion). All agg terms are weighted
// sums of SQUARES of the 20 moments:
//   agg0 = S^2
//   agg1 = |V|^2
//   agg2 = 1.5*||M||_F^2 - 0.5*S^2
//   agg3 = 2.5*||T||^2   - 1.5*|V|^2
// Then h = silu(agg @ w1^T + b1), o = h @ w2^T + b2, LayerNorm(o).

#define B_   4
#define N_   160
#define R_   64
#define EMB_ 128
#define HID_ 128
#define EPS_LN 1e-5f

__global__ __launch_bounds__(256)
void tba_fused(const float* __restrict__ rbf,     // (B,N,N,R)
               const float* __restrict__ r_hat,   // (B,N,N,3)
               const float* __restrict__ mask,    // (B,N,N)
               const float* __restrict__ w_rad,   // (1,R)
               const float* __restrict__ b_rad,   // (1,)
               const float* __restrict__ w1,      // (HID,4)
               const float* __restrict__ b1,      // (HID,)
               const float* __restrict__ w2,      // (EMB,HID)
               const float* __restrict__ b2,      // (EMB,)
               const float* __restrict__ gamma,   // (EMB,)
               const float* __restrict__ beta,    // (EMB,)
               float* __restrict__ out)           // (B,N,EMB)
{
    __shared__ float s_w[N_];          // sigmoid (pre-mask)
    __shared__ float s_mask[N_];
    __shared__ float s_rh[N_ * 3];
    __shared__ float s_red[8][20];
    __shared__ float s_val[20];
    __shared__ float s_agg[4];
    __shared__ float s_h[HID_];
    __shared__ float s_o[EMB_];
    __shared__ float s_ln[4][2];

    const int tid  = threadIdx.x;
    const int lane = tid & 31;
    const int warp = tid >> 5;
    const int row  = blockIdx.x;
    const float brad = b_rad[0];

    // 8 lanes per j-row; lane c owns w_rad float4s c and c+8.
    const int c = lane & 7;
    const float4* wr4 = reinterpret_cast<const float4*>(w_rad);
    const float4 wr0 = wr4[c];
    const float4 wr1 = wr4[c + 8];

    const float4* rbf4 =
        reinterpret_cast<const float4*>(rbf + (size_t)row * (N_ * R_));

    // ---- Phase A front batch: 10 rbf LDG.128 per thread + mask row (40
    // float4) + r_hat row (120 float4), all independent (deep MLP).
    const int jb = warp * 20 + (lane >> 3);
    float4 a0[5], a1[5];
    #pragma unroll
    for (int p = 0; p < 5; ++p) {
        const size_t base = (size_t)(jb + 4 * p) * (R_ / 4);
        a0[p] = rbf4[base + c];
        a1[p] = rbf4[base + c + 8];
    }
    float4 mrow, rhv;
    if (tid < 40)
        mrow = reinterpret_cast<const float4*>(mask + (size_t)row * N_)[tid];
    if (tid < 120)
        rhv = reinterpret_cast<const float4*>(r_hat + (size_t)row * (N_ * 3))[tid];

    if (tid < 40)  reinterpret_cast<float4*>(s_mask)[tid] = mrow;
    if (tid < 120) reinterpret_cast<float4*>(s_rh)[tid]   = rhv;

    #pragma unroll
    for (int p = 0; p < 5; ++p) {
        float v = a0[p].x * wr0.x;
        v = fmaf(a0[p].y, wr0.y, v);
        v = fmaf(a0[p].z, wr0.z, v);
        v = fmaf(a0[p].w, wr0.w, v);
        v = fmaf(a1[p].x, wr1.x, v);
        v = fmaf(a1[p].y, wr1.y, v);
        v = fmaf(a1[p].z, wr1.z, v);
        v = fmaf(a1[p].w, wr1.w, v);
        v += __shfl_xor_sync(0xffffffffu, v, 1);
        v += __shfl_xor_sync(0xffffffffu, v, 2);
        v += __shfl_xor_sync(0xffffffffu, v, 4);
        if (c == 0)
            s_w[jb + 4 * p] = __frcp_rn(1.f + __expf(-(v + brad)));
    }
    __syncthreads();

    // ---- Phase B: weighted direction moments (20 accumulators), all
    // operands from smem.
    float acc[20];
    #pragma unroll
    for (int q = 0; q < 20; ++q) acc[q] = 0.f;
    if (tid < N_) {
        const float w = s_w[tid] * s_mask[tid];
        const float x = s_rh[3 * tid];
        const float y = s_rh[3 * tid + 1];
        const float z = s_rh[3 * tid + 2];
        const float wx = w * x, wy = w * y, wz = w * z;
        const float wxx = wx * x, wyy = wy * y, wzz = wz * z;
        const float wxy = wx * y, wxz = wx * z, wyz = wy * z;
        acc[0]  = w;
        acc[1]  = wx;  acc[2]  = wy;  acc[3]  = wz;
        acc[4]  = wxx; acc[5]  = wyy; acc[6]  = wzz;
        acc[7]  = wxy; acc[8]  = wxz; acc[9]  = wyz;
        acc[10] = wxx * x; acc[11] = wyy * y; acc[12] = wzz * z;
        acc[13] = wxx * y; acc[14] = wxx * z;
        acc[15] = wyy * x; acc[16] = wyy * z;
        acc[17] = wzz * x; acc[18] = wzz * y;
        acc[19] = wxy * z;
    }
    // Packed 4-group reduce: 6 shuffles per 4 moments (30 total).
    #pragma unroll
    for (int g = 0; g < 5; ++g) {
        const int b = 4 * g;
        float keepA = (lane & 1) ? acc[b + 1] : acc[b + 0];
        float sendA = (lane & 1) ? acc[b + 0] : acc[b + 1];
        keepA += __shfl_xor_sync(0xffffffffu, sendA, 1);
        float keepB = (lane & 1) ? acc[b + 3] : acc[b + 2];
        float sendB = (lane & 1) ? acc[b + 2] : acc[b + 3];
        keepB += __shfl_xor_sync(0xffffffffu, sendB, 1);
        float keep = (lane & 2) ? keepB : keepA;
        float send = (lane & 2) ? keepA : keepB;
        keep += __shfl_xor_sync(0xffffffffu, send, 2);
        keep += __shfl_xor_sync(0xffffffffu, keep, 4);
        keep += __shfl_xor_sync(0xffffffffu, keep, 8);
        keep += __shfl_xor_sync(0xffffffffu, keep, 16);
        if (lane < 4) s_red[warp][b + lane] = keep;
    }
    __syncthreads();

    // ---- Combine: warp 0 lane q<20 sums 8 partials and squares with coef.
    if (warp == 0) {
        if (lane < 20) {
            float m = 0.f;
            #pragma unroll
            for (int u = 0; u < 8; ++u) m += s_red[u][lane];
            // coef: q0:1, q1-6:1, q7-9:2, q10-12:1, q13-18:3, q19:6
            float cf = 1.f;
            if (lane >= 7 && lane <= 9) cf = 2.f;
            else if (lane >= 13 && lane <= 18) cf = 3.f;
            else if (lane == 19) cf = 6.f;
            s_val[lane] = cf * m * m;
        }
        __syncwarp();
        if (lane == 0) {
            const float S2 = s_val[0];
            const float V2 = s_val[1] + s_val[2] + s_val[3];
            float Q2 = 0.f, Q3 = 0.f;
            #pragma unroll
            for (int q = 4; q < 10; ++q) Q2 += s_val[q];
            #pragma unroll
            for (int q = 10; q < 20; ++q) Q3 += s_val[q];
            s_agg[0] = S2;
            s_agg[1] = V2;
            s_agg[2] = 1.5f * Q2 - 0.5f * S2;
            s_agg[3] = 2.5f * Q3 - 1.5f * V2;
        }
    }
    __syncthreads();

    // ---- Phase C: h = silu(agg @ w1^T + b1). First 128 threads.
    if (tid < HID_) {
        const float4 wv1 = reinterpret_cast<const float4*>(w1)[tid];
        float hv = fmaf(s_agg[0], wv1.x,
                   fmaf(s_agg[1], wv1.y,
                   fmaf(s_agg[2], wv1.z,
                   fmaf(s_agg[3], wv1.w, b1[tid]))));
        hv = hv * __frcp_rn(1.f + __expf(-hv));
        s_h[tid] = hv;
    }
    __syncthreads();

    // Per-lane h slice in registers.
    const float4 hv = reinterpret_cast<const float4*>(s_h)[lane];

    // ---- GEMV: warp w handles outputs e = 16w..16w+15, paired (even lanes
    // carry e0 partials, odd e1): 5 shuffles per 2 outputs.
    const float4* w2v = reinterpret_cast<const float4*>(w2);
    #pragma unroll
    for (int ee = 0; ee < 8; ++ee) {
        const int e0 = warp * 16 + 2 * ee;
        const float4 wv0 = w2v[e0 * 32 + lane];
        const float4 wv1 = w2v[(e0 + 1) * 32 + lane];
        float acc0 = fmaf(wv0.x, hv.x, fmaf(wv0.y, hv.y,
                     fmaf(wv0.z, hv.z, wv0.w * hv.w)));
        float acc1 = fmaf(wv1.x, hv.x, fmaf(wv1.y, hv.y,
                     fmaf(wv1.z, hv.z, wv1.w * hv.w)));
        float keep = (lane & 1) ? acc1 : acc0;
        float send = (lane & 1) ? acc0 : acc1;
        keep += __shfl_xor_sync(0xffffffffu, send, 1);
        keep += __shfl_xor_sync(0xffffffffu, keep, 2);
        keep += __shfl_xor_sync(0xffffffffu, keep, 4);
        keep += __shfl_xor_sync(0xffffffffu, keep, 8);
        keep += __shfl_xor_sync(0xffffffffu, keep, 16);
        if (lane < 2) s_o[e0 + lane] = keep;
    }
    __syncthreads();

    // ---- LayerNorm: fused sum/sumsq packed reduce (one barrier round).
    float ov = 0.f;
    if (tid < EMB_) ov = s_o[tid] + b2[tid];

    if (warp < 4) {
        const float sv = ov, ssv = ov * ov;
        float keep = (lane & 1) ? ssv : sv;
        float send = (lane & 1) ? sv : ssv;
        keep += __shfl_xor_sync(0xffffffffu, send, 1);
        keep += __shfl_xor_sync(0xffffffffu, keep, 2);
        keep += __shfl_xor_sync(0xffffffffu, keep, 4);
        keep += __shfl_xor_sync(0xffffffffu, keep, 8);
        keep += __shfl_xor_sync(0xffffffffu, keep, 16);
        if (lane < 2) s_ln[warp][lane] = keep;   // [0]=sum, [1]=sumsq
    }
    __syncthreads();

    if (tid < EMB_) {
        const float Ssum  = s_ln[0][0] + s_ln[1][0] + s_ln[2][0] + s_ln[3][0];
        const float SSsum = s_ln[0][1] + s_ln[1][1] + s_ln[2][1] + s_ln[3][1];
        const float mu  = Ssum * (1.f / EMB_);
        const float var = SSsum * (1.f / EMB_) - mu * mu;
        const float y = (ov - mu) * rsqrtf(var + EPS_LN);
        out[(size_t)row * EMB_ + tid] = fmaf(y, gamma[tid], beta[tid]);
    }
}

extern "C" void kernel_launch(void* const* d_in, const int* in_sizes, int n_in,
                              void* d_out, int out_size)
{
    const float* rbf    = (const float*)d_in[0];
    const float* r_hat  = (const float*)d_in[1];
    const float* mask   = (const float*)d_in[2];
    const float* w_rad  = (const float*)d_in[3];
    const float* b_rad  = (const float*)d_in[4];
    const float* w1     = (const float*)d_in[5];
    const float* b1     = (const float*)d_in[6];
    const float* w2     = (const float*)d_in[7];
    const float* b2     = (const float*)d_in[8];
    const float* gamma  = (const float*)d_in[9];
    const float* beta   = (const float*)d_in[10];
    float* out = (float*)d_out;

    tba_fused<<<B_ * N_, 256>>>(rbf, r_hat, mask, w_rad, b_rad,
                                w1, b1, w2, b2, gamma, beta, out);
}

// round 12
// speedup vs baseline: 2.9134x; 1.4090x over previous
#include <cuda_runtime.h>

// ThreeBodyAggregation — moment-factorized, fully fused, 1 row per block.
//
// agg_l(b,i) = sum_{j,k} w_j w_k P_l(u_j.u_k) computed exactly via weighted
// direction moments (Legendre monomial expansion). All agg terms are weighted
// sums of SQUARES of the 20 moments:
//   agg0 = S^2
//   agg1 = |V|^2
//   agg2 = 1.5*||M||_F^2 - 0.5*S^2
//   agg3 = 2.5*||T||^2   - 1.5*|V|^2
// Then h = silu(agg @ w1^T + b1), o = h @ w2^T + b2, LayerNorm(o).
//
// Register budget is capped (launch_bounds minBlocks=5) so the 640-block grid
// fits in ONE wave (148 SMs x 5 CTAs = 740 >= 640); Phase A loads are split
// into two half-batches (max 6 float4 live) to fit 48 regs without spills.

#define B_   4
#define N_   160
#define R_   64
#define EMB_ 128
#define HID_ 128
#define EPS_LN 1e-5f

__global__ __launch_bounds__(256, 5)
void tba_fused(const float* __restrict__ rbf,     // (B,N,N,R)
               const float* __restrict__ r_hat,   // (B,N,N,3)
               const float* __restrict__ mask,    // (B,N,N)
               const float* __restrict__ w_rad,   // (1,R)
               const float* __restrict__ b_rad,   // (1,)
               const float* __restrict__ w1,      // (HID,4)
               const float* __restrict__ b1,      // (HID,)
               const float* __restrict__ w2,      // (EMB,HID)
               const float* __restrict__ b2,      // (EMB,)
               const float* __restrict__ gamma,   // (EMB,)
               const float* __restrict__ beta,    // (EMB,)
               float* __restrict__ out)           // (B,N,EMB)
{
    __shared__ float s_w[N_];          // sigmoid (pre-mask)
    __shared__ float s_mask[N_];
    __shared__ float s_rh[N_ * 3];
    __shared__ float s_red[8][20];
    __shared__ float s_val[20];
    __shared__ float s_agg[4];
    __shared__ float s_h[HID_];
    __shared__ float s_o[EMB_];
    __shared__ float s_ln[4][2];

    const int tid  = threadIdx.x;
    const int lane = tid & 31;
    const int warp = tid >> 5;
    const int row  = blockIdx.x;
    const float brad = b_rad[0];

    // ---- mask + r_hat rows first (coalesced float4; done before Phase B).
    if (tid < 40)
        reinterpret_cast<float4*>(s_mask)[tid] =
            reinterpret_cast<const float4*>(mask + (size_t)row * N_)[tid];
    if (tid < 120)
        reinterpret_cast<float4*>(s_rh)[tid] =
            reinterpret_cast<const float4*>(r_hat + (size_t)row * (N_ * 3))[tid];

    // 8 lanes per j-row; lane c owns w_rad float4s c and c+8.
    const int c = lane & 7;
    const float4* wr4 = reinterpret_cast<const float4*>(w_rad);
    const float4 wr0 = wr4[c];
    const float4 wr1 = wr4[c + 8];

    const float4* rbf4 =
        reinterpret_cast<const float4*>(rbf + (size_t)row * (N_ * R_));

    // ---- Phase A: warp w covers j = 20w..20w+19; 4 j-rows per pass
    // (lane>>3 picks the row), 5 passes in two half-batches (3 + 2 passes,
    // i.e. 6 then 4 LDG.128 per thread; max 6 float4 live -> 48-reg fit).
    const int jb = warp * 20 + (lane >> 3);
    {
        float4 a0[3], a1[3];
        #pragma unroll
        for (int p = 0; p < 3; ++p) {
            const size_t base = (size_t)(jb + 4 * p) * (R_ / 4);
            a0[p] = rbf4[base + c];
            a1[p] = rbf4[base + c + 8];
        }
        #pragma unroll
        for (int p = 0; p < 3; ++p) {
            float v = a0[p].x * wr0.x;
            v = fmaf(a0[p].y, wr0.y, v);
            v = fmaf(a0[p].z, wr0.z, v);
            v = fmaf(a0[p].w, wr0.w, v);
            v = fmaf(a1[p].x, wr1.x, v);
            v = fmaf(a1[p].y, wr1.y, v);
            v = fmaf(a1[p].z, wr1.z, v);
            v = fmaf(a1[p].w, wr1.w, v);
            v += __shfl_xor_sync(0xffffffffu, v, 1);
            v += __shfl_xor_sync(0xffffffffu, v, 2);
            v += __shfl_xor_sync(0xffffffffu, v, 4);
            if (c == 0)
                s_w[jb + 4 * p] = __frcp_rn(1.f + __expf(-(v + brad)));
        }
    }
    {
        float4 a0[2], a1[2];
        #pragma unroll
        for (int p = 0; p < 2; ++p) {
            const size_t base = (size_t)(jb + 4 * (p + 3)) * (R_ / 4);
            a0[p] = rbf4[base + c];
            a1[p] = rbf4[base + c + 8];
        }
        #pragma unroll
        for (int p = 0; p < 2; ++p) {
            float v = a0[p].x * wr0.x;
            v = fmaf(a0[p].y, wr0.y, v);
            v = fmaf(a0[p].z, wr0.z, v);
            v = fmaf(a0[p].w, wr0.w, v);
            v = fmaf(a1[p].x, wr1.x, v);
            v = fmaf(a1[p].y, wr1.y, v);
            v = fmaf(a1[p].z, wr1.z, v);
            v = fmaf(a1[p].w, wr1.w, v);
            v += __shfl_xor_sync(0xffffffffu, v, 1);
            v += __shfl_xor_sync(0xffffffffu, v, 2);
            v += __shfl_xor_sync(0xffffffffu, v, 4);
            if (c == 0)
                s_w[jb + 4 * (p + 3)] = __frcp_rn(1.f + __expf(-(v + brad)));
        }
    }
    __syncthreads();

    // ---- Phase B: weighted direction moments (20 accumulators), all
    // operands from smem.
    float acc[20];
    #pragma unroll
    for (int q = 0; q < 20; ++q) acc[q] = 0.f;
    if (tid < N_) {
        const float w = s_w[tid] * s_mask[tid];
        const float x = s_rh[3 * tid];
        const float y = s_rh[3 * tid + 1];
        const float z = s_rh[3 * tid + 2];
        const float wx = w * x, wy = w * y, wz = w * z;
        const float wxx = wx * x, wyy = wy * y, wzz = wz * z;
        const float wxy = wx * y, wxz = wx * z, wyz = wy * z;
        acc[0]  = w;
        acc[1]  = wx;  acc[2]  = wy;  acc[3]  = wz;
        acc[4]  = wxx; acc[5]  = wyy; acc[6]  = wzz;
        acc[7]  = wxy; acc[8]  = wxz; acc[9]  = wyz;
        acc[10] = wxx * x; acc[11] = wyy * y; acc[12] = wzz * z;
        acc[13] = wxx * y; acc[14] = wxx * z;
        acc[15] = wyy * x; acc[16] = wyy * z;
        acc[17] = wzz * x; acc[18] = wzz * y;
        acc[19] = wxy * z;
    }
    // Packed 4-group reduce: 6 shuffles per 4 moments (30 total).
    #pragma unroll
    for (int g = 0; g < 5; ++g) {
        const int b = 4 * g;
        float keepA = (lane & 1) ? acc[b + 1] : acc[b + 0];
        float sendA = (lane & 1) ? acc[b + 0] : acc[b + 1];
        keepA += __shfl_xor_sync(0xffffffffu, sendA, 1);
        float keepB = (lane & 1) ? acc[b + 3] : acc[b + 2];
        float sendB = (lane & 1) ? acc[b + 2] : acc[b + 3];
        keepB += __shfl_xor_sync(0xffffffffu, sendB, 1);
        float keep = (lane & 2) ? keepB : keepA;
        float send = (lane & 2) ? keepA : keepB;
        keep += __shfl_xor_sync(0xffffffffu, send, 2);
        keep += __shfl_xor_sync(0xffffffffu, keep, 4);
        keep += __shfl_xor_sync(0xffffffffu, keep, 8);
        keep += __shfl_xor_sync(0xffffffffu, keep, 16);
        if (lane < 4) s_red[warp][b + lane] = keep;
    }
    __syncthreads();

    // ---- Combine: warp 0 lane q<20 sums 8 partials, squares with coef.
    if (warp == 0) {
        if (lane < 20) {
            float m = 0.f;
            #pragma unroll
            for (int u = 0; u < 8; ++u) m += s_red[u][lane];
            // coef: q0:1, q1-6:1, q7-9:2, q10-12:1, q13-18:3, q19:6
            float cf = 1.f;
            if (lane >= 7 && lane <= 9) cf = 2.f;
            else if (lane >= 13 && lane <= 18) cf = 3.f;
            else if (lane == 19) cf = 6.f;
            s_val[lane] = cf * m * m;
        }
        __syncwarp();
        if (lane == 0) {
            const float S2 = s_val[0];
            const float V2 = s_val[1] + s_val[2] + s_val[3];
            float Q2 = 0.f, Q3 = 0.f;
            #pragma unroll
            for (int q = 4; q < 10; ++q) Q2 += s_val[q];
            #pragma unroll
            for (int q = 10; q < 20; ++q) Q3 += s_val[q];
            s_agg[0] = S2;
            s_agg[1] = V2;
            s_agg[2] = 1.5f * Q2 - 0.5f * S2;
            s_agg[3] = 2.5f * Q3 - 1.5f * V2;
        }
    }
    __syncthreads();

    // ---- Phase C: h = silu(agg @ w1^T + b1). First 128 threads.
    if (tid < HID_) {
        const float4 wv1 = reinterpret_cast<const float4*>(w1)[tid];
        float hv = fmaf(s_agg[0], wv1.x,
                   fmaf(s_agg[1], wv1.y,
                   fmaf(s_agg[2], wv1.z,
                   fmaf(s_agg[3], wv1.w, b1[tid]))));
        hv = hv * __frcp_rn(1.f + __expf(-hv));
        s_h[tid] = hv;
    }
    __syncthreads();

    // Per-lane h slice in registers.
    const float4 hv = reinterpret_cast<const float4*>(s_h)[lane];

    // ---- GEMV: warp w handles outputs e = 16w..16w+15, paired (even lanes
    // carry e0 partials, odd e1): 5 shuffles per 2 outputs.
    const float4* w2v = reinterpret_cast<const float4*>(w2);
    #pragma unroll
    for (int ee = 0; ee < 8; ++ee) {
        const int e0 = warp * 16 + 2 * ee;
        const float4 wv0 = w2v[e0 * 32 + lane];
        const float4 wv1 = w2v[(e0 + 1) * 32 + lane];
        float acc0 = fmaf(wv0.x, hv.x, fmaf(wv0.y, hv.y,
                     fmaf(wv0.z, hv.z, wv0.w * hv.w)));
        float acc1 = fmaf(wv1.x, hv.x, fmaf(wv1.y, hv.y,
                     fmaf(wv1.z, hv.z, wv1.w * hv.w)));
        float keep = (lane & 1) ? acc1 : acc0;
        float send = (lane & 1) ? acc0 : acc1;
        keep += __shfl_xor_sync(0xffffffffu, send, 1);
        keep += __shfl_xor_sync(0xffffffffu, keep, 2);
        keep += __shfl_xor_sync(0xffffffffu, keep, 4);
        keep += __shfl_xor_sync(0xffffffffu, keep, 8);
        keep += __shfl_xor_sync(0xffffffffu, keep, 16);
        if (lane < 2) s_o[e0 + lane] = keep;
    }
    __syncthreads();

    // ---- LayerNorm: fused sum/sumsq packed reduce (one barrier round).
    float ov = 0.f;
    if (tid < EMB_) ov = s_o[tid] + b2[tid];

    if (warp < 4) {
        const float sv = ov, ssv = ov * ov;
        float keep = (lane & 1) ? ssv : sv;
        float send = (lane & 1) ? sv : ssv;
        keep += __shfl_xor_sync(0xffffffffu, send, 1);
        keep += __shfl_xor_sync(0xffffffffu, keep, 2);
        keep += __shfl_xor_sync(0xffffffffu, keep, 4);
        keep += __shfl_xor_sync(0xffffffffu, keep, 8);
        keep += __shfl_xor_sync(0xffffffffu, keep, 16);
        if (lane < 2) s_ln[warp][lane] = keep;   // [0]=sum, [1]=sumsq
    }
    __syncthreads();

    if (tid < EMB_) {
        const float Ssum  = s_ln[0][0] + s_ln[1][0] + s_ln[2][0] + s_ln[3][0];
        const float SSsum = s_ln[0][1] + s_ln[1][1] + s_ln[2][1] + s_ln[3][1];
        const float mu  = Ssum * (1.f / EMB_);
        const float var = SSsum * (1.f / EMB_) - mu * mu;
        const float y = (ov - mu) * rsqrtf(var + EPS_LN);
        out[(size_t)row * EMB_ + tid] = fmaf(y, gamma[tid], beta[tid]);
    }
}

extern "C" void kernel_launch(void* const* d_in, const int* in_sizes, int n_in,
                              void* d_out, int out_size)
{
    const float* rbf    = (const float*)d_in[0];
    const float* r_hat  = (const float*)d_in[1];
    const float* mask   = (const float*)d_in[2];
    const float* w_rad  = (const float*)d_in[3];
    const float* b_rad  = (const float*)d_in[4];
    const float* w1     = (const float*)d_in[5];
    const float* b1     = (const float*)d_in[6];
    const float* w2     = (const float*)d_in[7];
    const float* b2     = (const float*)d_in[8];
    const float* gamma  = (const float*)d_in[9];
    const float* beta   = (const float*)d_in[10];
    float* out = (float*)d_out;

    tba_fused<<<B_ * N_, 256>>>(rbf, r_hat, mask, w_rad, b_rad,
                                w1, b1, w2, b2, gamma, beta, out);
}